// round 13
// baseline (speedup 1.0000x reference)
#include <cuda_runtime.h>

// DifferentiableCensus: out = (1/9) * sum_{3x3, edge-clamped} sigmoid(neighbor - center)
// x: (16,3,512,512) f32 -> 48 independent 512x512 images.
//
// Round 13 (= R12 with legal PTX): L2 residency engineering.
//  - input loads:  ld.global.nc.L2::cache_hint + createpolicy evict_last
//    (bare .L2::evict_last modifier requires 256-bit loads on sm_103a ptxas;
//     the cache_hint/createpolicy form works at any width)
//  - output stores: __stcs (evict_first -> stream through L2, don't evict input)
// Datapath = leanest proven (R8/R11): f32 tanh.approx, edge-sharing (each
// pixel-pair edge once, reverse = negation), out = 0.5 + T/18.
// 16 rows/thread, grid 1536 = one balanced wave.

static constexpr int H = 512;
static constexpr int W = 512;
static constexpr int ROWS_PER_THREAD = 16;
static constexpr int BLOCK_X = 128;            // 128 threads * 4 cols = 512 cols

__device__ __forceinline__ float tanh_ap(float v) {
    float r;
    asm("tanh.approx.f32 %0, %1;" : "=f"(r) : "f"(v));
    return r;
}

__device__ __forceinline__ unsigned long long mk_evict_last_policy() {
    unsigned long long pol;
    asm("createpolicy.fractional.L2::evict_last.b64 %0, 1.0;" : "=l"(pol));
    return pol;
}

__device__ __forceinline__ float4 ldg_el4(const float* p, unsigned long long pol) {
    float4 v;
    asm("ld.global.nc.L2::cache_hint.v4.f32 {%0,%1,%2,%3}, [%4], %5;"
        : "=f"(v.x), "=f"(v.y), "=f"(v.z), "=f"(v.w) : "l"(p), "l"(pol));
    return v;
}

__device__ __forceinline__ float ldg_el1(const float* p, unsigned long long pol) {
    float v;
    asm("ld.global.nc.L2::cache_hint.f32 %0, [%1], %2;" : "=f"(v) : "l"(p), "l"(pol));
    return v;
}

__device__ __forceinline__ void load_row(const float* __restrict__ row,
                                         int c0, int cl, int cr,
                                         unsigned long long pol, float v[6]) {
    // v[0]=col c0-1 (clamped), v[1..4]=c0..c0+3, v[5]=c0+4 (clamped); prescaled 0.5
    const float4 m = ldg_el4(row + c0, pol);
    v[0] = 0.5f * ldg_el1(row + cl, pol);
    v[1] = 0.5f * m.x;
    v[2] = 0.5f * m.y;
    v[3] = 0.5f * m.z;
    v[4] = 0.5f * m.w;
    v[5] = 0.5f * ldg_el1(row + cr, pol);
}

__global__ __launch_bounds__(BLOCK_X)
void census_kernel(const float* __restrict__ x, float* __restrict__ out) {
    const int c0  = threadIdx.x * 4;
    const int r0  = blockIdx.y * ROWS_PER_THREAD;
    const int img = blockIdx.z;

    const unsigned long long pol = mk_evict_last_policy();

    const float* __restrict__ xi = x   + (size_t)img * H * W;
    float* __restrict__       oi = out + (size_t)img * H * W;

    const int cl = max(c0 - 1, 0);
    const int cr = min(c0 + 4, W - 1);

    float b[6];
    load_row(xi + (size_t)r0 * W, c0, cl, cr, pol, b);

    // Priming carries from row r0-1 (p): S/SE/SW edge tanh + p's halo lanes.
    float pS[4], pDR[4], pDL[4], pl, pr;
    {
        float p[6];
        load_row(xi + (size_t)max(r0 - 1, 0) * W, c0, cl, cr, pol, p);
        #pragma unroll
        for (int i = 0; i < 4; i++) {
            pS[i]  = tanh_ap(b[i + 1] - p[i + 1]);
            pDR[i] = tanh_ap(b[i + 2] - p[i + 1]);
            pDL[i] = tanh_ap(b[i]     - p[i + 1]);
        }
        pl = p[0]; pr = p[5];
    }

    #pragma unroll
    for (int k = 0; k < ROWS_PER_THREAD; k++) {
        const int r = r0 + k;
        float n[6];
        load_row(xi + (size_t)min(r + 1, H - 1) * W, c0, cl, cr, pol, n);

        float tS[4], tDR[4], tDL[4], tE[4];
        #pragma unroll
        for (int i = 0; i < 4; i++) {
            tS[i]  = tanh_ap(n[i + 1] - b[i + 1]); // S
            tDR[i] = tanh_ap(n[i + 2] - b[i + 1]); // SE
            tDL[i] = tanh_ap(n[i]     - b[i + 1]); // SW
            tE[i]  = tanh_ap(b[i + 2] - b[i + 1]); // E
        }
        const float tW0  = tanh_ap(b[0] - b[1]);   // W  halo (col c0)
        const float tUL0 = tanh_ap(pl   - b[1]);   // NW halo (col c0)
        const float tUR3 = tanh_ap(pr   - b[4]);   // NE halo (col c0+3)

        // Signed sums: forward edges +, reverse of previously-computed edges -.
        const float T0 = (tS[0] + tDR[0]) + (tDL[0] - pS[0])
                       + (tE[0] + tW0)    + (tUL0   - pDL[1]);
        const float T1 = (tS[1] + tDR[1]) + (tDL[1] - pS[1])
                       + (tE[1] - tE[0])  - (pDR[0] + pDL[2]);
        const float T2 = (tS[2] + tDR[2]) + (tDL[2] - pS[2])
                       + (tE[2] - tE[1])  - (pDR[1] + pDL[3]);
        const float T3 = (tS[3] + tDR[3]) + (tDL[3] - pS[3])
                       + (tE[3] - tE[2])  + (tUR3   - pDR[2]);

        float4 o;
        o.x = fmaf(T0, 1.0f / 18.0f, 0.5f);
        o.y = fmaf(T1, 1.0f / 18.0f, 0.5f);
        o.z = fmaf(T2, 1.0f / 18.0f, 0.5f);
        o.w = fmaf(T3, 1.0f / 18.0f, 0.5f);
        // Evict-first store: stream output through L2 without evicting input.
        __stcs(reinterpret_cast<float4*>(oi + (size_t)r * W + c0), o);

        // Roll: keep old center row's halo lanes; carry forward edges.
        pl = b[0]; pr = b[5];
        #pragma unroll
        for (int i = 0; i < 6; i++) b[i] = n[i];
        #pragma unroll
        for (int i = 0; i < 4; i++) { pS[i] = tS[i]; pDR[i] = tDR[i]; pDL[i] = tDL[i]; }
    }
}

extern "C" void kernel_launch(void* const* d_in, const int* in_sizes, int n_in,
                              void* d_out, int out_size) {
    (void)in_sizes; (void)n_in; (void)out_size;
    const float* x = (const float*)d_in[0];
    float* out = (float*)d_out;

    dim3 block(BLOCK_X, 1, 1);
    dim3 grid(1, H / ROWS_PER_THREAD, 16 * 3);   // 1536 CTAs ~= one balanced wave
    census_kernel<<<grid, block>>>(x, out);
}

// round 14
// speedup vs baseline: 1.0028x; 1.0028x over previous
#include <cuda_runtime.h>

// DifferentiableCensus: out = (1/9) * sum_{3x3, edge-clamped} sigmoid(neighbor - center)
// x: (16,3,512,512) f32 -> 48 independent 512x512 images.
//
// Round 14: transaction widening on top of the best (R11) config.
//  - 8 cols/thread via 256-bit loads (ld.global.nc.v8.b32): half the load
//    and store instructions per pixel, denser edge sharing (35 tanh / 8 px).
//  - 128-thread CTA = 64 cols-threads x 2 row-strips of 8 -> 1536 CTAs,
//    one balanced wave (same as R11).
//  - __stcs float4 stores (evict_first) - kept from R11 (won there).
//  - f32 tanh.approx datapath, each pixel-pair edge computed once
//    (reverse = negation), out = 0.5 + T/18.

static constexpr int H = 512;
static constexpr int W = 512;
static constexpr int ROWS_PER_THREAD = 8;
static constexpr int BLOCK = 128;              // 64 col-threads x 2 row strips

__device__ __forceinline__ float tanh_ap(float v) {
    float r;
    asm("tanh.approx.f32 %0, %1;" : "=f"(r) : "f"(v));
    return r;
}

// v[0]=col c0-1 (clamped), v[1..8]=c0..c0+7, v[9]=c0+8 (clamped); prescaled 0.5
__device__ __forceinline__ void load_row(const float* __restrict__ row,
                                         int c0, int cl, int cr, float v[10]) {
    unsigned a0, a1, a2, a3, a4, a5, a6, a7;
    asm("ld.global.nc.v8.b32 {%0,%1,%2,%3,%4,%5,%6,%7}, [%8];"
        : "=r"(a0), "=r"(a1), "=r"(a2), "=r"(a3),
          "=r"(a4), "=r"(a5), "=r"(a6), "=r"(a7)
        : "l"(row + c0));
    v[0] = 0.5f * __ldg(row + cl);
    v[1] = 0.5f * __uint_as_float(a0);
    v[2] = 0.5f * __uint_as_float(a1);
    v[3] = 0.5f * __uint_as_float(a2);
    v[4] = 0.5f * __uint_as_float(a3);
    v[5] = 0.5f * __uint_as_float(a4);
    v[6] = 0.5f * __uint_as_float(a5);
    v[7] = 0.5f * __uint_as_float(a6);
    v[8] = 0.5f * __uint_as_float(a7);
    v[9] = 0.5f * __ldg(row + cr);
}

__global__ __launch_bounds__(BLOCK)
void census_kernel(const float* __restrict__ x, float* __restrict__ out) {
    const int tx  = threadIdx.x & 63;                 // column-thread 0..63
    const int ty  = threadIdx.x >> 6;                 // strip 0..1
    const int c0  = tx * 8;
    const int r0  = blockIdx.y * (2 * ROWS_PER_THREAD) + ty * ROWS_PER_THREAD;
    const int img = blockIdx.z;

    const float* __restrict__ xi = x   + (size_t)img * H * W;
    float* __restrict__       oi = out + (size_t)img * H * W;

    const int cl = max(c0 - 1, 0);
    const int cr = min(c0 + 8, W - 1);

    float b[10];
    load_row(xi + (size_t)r0 * W, c0, cl, cr, b);

    // Priming carries from row r0-1 (p): S/SE/SW edge tanh + p's halo lanes.
    float pS[8], pDR[8], pDL[8], pl, pr;
    {
        float p[10];
        load_row(xi + (size_t)max(r0 - 1, 0) * W, c0, cl, cr, p);
        #pragma unroll
        for (int i = 0; i < 8; i++) {
            pS[i]  = tanh_ap(b[i + 1] - p[i + 1]);
            pDR[i] = tanh_ap(b[i + 2] - p[i + 1]);
            pDL[i] = tanh_ap(b[i]     - p[i + 1]);
        }
        pl = p[0]; pr = p[9];
    }

    #pragma unroll
    for (int k = 0; k < ROWS_PER_THREAD; k++) {
        const int r = r0 + k;
        float n[10];
        load_row(xi + (size_t)min(r + 1, H - 1) * W, c0, cl, cr, n);

        float tS[8], tDR[8], tDL[8], tE[8];
        #pragma unroll
        for (int i = 0; i < 8; i++) {
            tS[i]  = tanh_ap(n[i + 1] - b[i + 1]); // S
            tDR[i] = tanh_ap(n[i + 2] - b[i + 1]); // SE
            tDL[i] = tanh_ap(n[i]     - b[i + 1]); // SW
            tE[i]  = tanh_ap(b[i + 2] - b[i + 1]); // E
        }
        const float tW0  = tanh_ap(b[0] - b[1]);   // W  halo (col c0)
        const float tUL0 = tanh_ap(pl   - b[1]);   // NW halo (col c0)
        const float tUR7 = tanh_ap(pr   - b[8]);   // NE halo (col c0+7)

        // Signed sums: forward edges +, reverse of previously-computed edges -.
        float T[8];
        T[0] = (tS[0] + tDR[0]) + (tDL[0] - pS[0])
             + (tE[0] + tW0)    + (tUL0   - pDL[1]);
        #pragma unroll
        for (int i = 1; i < 7; i++) {
            T[i] = (tS[i] + tDR[i]) + (tDL[i] - pS[i])
                 + (tE[i] - tE[i - 1]) - (pDR[i - 1] + pDL[i + 1]);
        }
        T[7] = (tS[7] + tDR[7]) + (tDL[7] - pS[7])
             + (tE[7] - tE[6])  + (tUR7   - pDR[6]);

        float4 o1, o2;
        o1.x = fmaf(T[0], 1.0f / 18.0f, 0.5f);
        o1.y = fmaf(T[1], 1.0f / 18.0f, 0.5f);
        o1.z = fmaf(T[2], 1.0f / 18.0f, 0.5f);
        o1.w = fmaf(T[3], 1.0f / 18.0f, 0.5f);
        o2.x = fmaf(T[4], 1.0f / 18.0f, 0.5f);
        o2.y = fmaf(T[5], 1.0f / 18.0f, 0.5f);
        o2.z = fmaf(T[6], 1.0f / 18.0f, 0.5f);
        o2.w = fmaf(T[7], 1.0f / 18.0f, 0.5f);
        float* orow = oi + (size_t)r * W + c0;
        __stcs(reinterpret_cast<float4*>(orow),     o1);
        __stcs(reinterpret_cast<float4*>(orow) + 1, o2);

        // Roll: keep old center row's halo lanes; carry forward edges.
        pl = b[0]; pr = b[9];
        #pragma unroll
        for (int i = 0; i < 10; i++) b[i] = n[i];
        #pragma unroll
        for (int i = 0; i < 8; i++) { pS[i] = tS[i]; pDR[i] = tDR[i]; pDL[i] = tDL[i]; }
    }
}

extern "C" void kernel_launch(void* const* d_in, const int* in_sizes, int n_in,
                              void* d_out, int out_size) {
    (void)in_sizes; (void)n_in; (void)out_size;
    const float* x = (const float*)d_in[0];
    float* out = (float*)d_out;

    dim3 block(BLOCK, 1, 1);
    dim3 grid(1, H / (2 * ROWS_PER_THREAD), 16 * 3);   // 1536 CTAs, one wave
    census_kernel<<<grid, block>>>(x, out);
}

// round 15
// speedup vs baseline: 1.0794x; 1.0763x over previous
#include <cuda_runtime.h>

// DifferentiableCensus: out = (1/9) * sum_{3x3, edge-clamped} sigmoid(neighbor - center)
// x: (16,3,512,512) f32 -> 48 independent 512x512 images.
//
// Round 15: R11 (best, 21.0us) + explicit software pipelining.
//  - Double-buffered row prefetch, distance 2: the LDG for row k+2 issues
//    before row k+1's tanh block, guaranteeing the L2-hit latency (~234cyc)
//    is covered by ~19 tanh + sums of the current row.
//  - Everything else identical to R11: f32 tanh.approx, edge-sharing (each
//    pixel-pair edge once, reverse = negation), out = 0.5 + T/18,
//    16 rows/thread, grid 1536 = one balanced wave, __stcs float4 stores.

static constexpr int H = 512;
static constexpr int W = 512;
static constexpr int ROWS_PER_THREAD = 16;
static constexpr int BLOCK_X = 128;            // 128 threads * 4 cols = 512 cols

__device__ __forceinline__ float tanh_ap(float v) {
    float r;
    asm("tanh.approx.f32 %0, %1;" : "=f"(r) : "f"(v));
    return r;
}

__device__ __forceinline__ void load_row(const float* __restrict__ row,
                                         int c0, int cl, int cr, float v[6]) {
    // v[0]=col c0-1 (clamped), v[1..4]=c0..c0+3, v[5]=c0+4 (clamped); prescaled 0.5
    const float4 m = __ldg(reinterpret_cast<const float4*>(row + c0));
    v[0] = 0.5f * __ldg(row + cl);
    v[1] = 0.5f * m.x;
    v[2] = 0.5f * m.y;
    v[3] = 0.5f * m.z;
    v[4] = 0.5f * m.w;
    v[5] = 0.5f * __ldg(row + cr);
}

__global__ __launch_bounds__(BLOCK_X)
void census_kernel(const float* __restrict__ x, float* __restrict__ out) {
    const int c0  = threadIdx.x * 4;
    const int r0  = blockIdx.y * ROWS_PER_THREAD;
    const int img = blockIdx.z;

    const float* __restrict__ xi = x   + (size_t)img * H * W;
    float* __restrict__       oi = out + (size_t)img * H * W;

    const int cl = max(c0 - 1, 0);
    const int cr = min(c0 + 4, W - 1);

    float b[6];
    load_row(xi + (size_t)r0 * W, c0, cl, cr, b);

    // Priming carries from row r0-1 (p): S/SE/SW edge tanh + p's halo lanes.
    float pS[4], pDR[4], pDL[4], pl, pr;
    {
        float p[6];
        load_row(xi + (size_t)max(r0 - 1, 0) * W, c0, cl, cr, p);
        #pragma unroll
        for (int i = 0; i < 4; i++) {
            pS[i]  = tanh_ap(b[i + 1] - p[i + 1]);
            pDR[i] = tanh_ap(b[i + 2] - p[i + 1]);
            pDL[i] = tanh_ap(b[i]     - p[i + 1]);
        }
        pl = p[0]; pr = p[5];
    }

    // Double-buffered "next row" prefetch. nbuf[k&1] holds row r0+k+1 at iter k.
    float nbuf[2][6];
    load_row(xi + (size_t)min(r0 + 1, H - 1) * W, c0, cl, cr, nbuf[0]);

    #pragma unroll
    for (int k = 0; k < ROWS_PER_THREAD; k++) {
        // Prefetch row r0+k+2 (used next iteration) BEFORE this row's tanh block.
        if (k < ROWS_PER_THREAD - 1) {
            load_row(xi + (size_t)min(r0 + k + 2, H - 1) * W, c0, cl, cr,
                     nbuf[(k + 1) & 1]);
        }
        const float* n = nbuf[k & 1];
        const int r = r0 + k;

        float tS[4], tDR[4], tDL[4], tE[4];
        #pragma unroll
        for (int i = 0; i < 4; i++) {
            tS[i]  = tanh_ap(n[i + 1] - b[i + 1]); // S
            tDR[i] = tanh_ap(n[i + 2] - b[i + 1]); // SE
            tDL[i] = tanh_ap(n[i]     - b[i + 1]); // SW
            tE[i]  = tanh_ap(b[i + 2] - b[i + 1]); // E
        }
        const float tW0  = tanh_ap(b[0] - b[1]);   // W  halo (col c0)
        const float tUL0 = tanh_ap(pl   - b[1]);   // NW halo (col c0)
        const float tUR3 = tanh_ap(pr   - b[4]);   // NE halo (col c0+3)

        // Signed sums: forward edges +, reverse of previously-computed edges -.
        const float T0 = (tS[0] + tDR[0]) + (tDL[0] - pS[0])
                       + (tE[0] + tW0)    + (tUL0   - pDL[1]);
        const float T1 = (tS[1] + tDR[1]) + (tDL[1] - pS[1])
                       + (tE[1] - tE[0])  - (pDR[0] + pDL[2]);
        const float T2 = (tS[2] + tDR[2]) + (tDL[2] - pS[2])
                       + (tE[2] - tE[1])  - (pDR[1] + pDL[3]);
        const float T3 = (tS[3] + tDR[3]) + (tDL[3] - pS[3])
                       + (tE[3] - tE[2])  + (tUR3   - pDR[2]);

        float4 o;
        o.x = fmaf(T0, 1.0f / 18.0f, 0.5f);
        o.y = fmaf(T1, 1.0f / 18.0f, 0.5f);
        o.z = fmaf(T2, 1.0f / 18.0f, 0.5f);
        o.w = fmaf(T3, 1.0f / 18.0f, 0.5f);
        // Evict-first store: stream output through L2 without evicting input.
        __stcs(reinterpret_cast<float4*>(oi + (size_t)r * W + c0), o);

        // Roll: keep old center row's halo lanes; carry forward edges.
        pl = b[0]; pr = b[5];
        #pragma unroll
        for (int i = 0; i < 6; i++) b[i] = n[i];
        #pragma unroll
        for (int i = 0; i < 4; i++) { pS[i] = tS[i]; pDR[i] = tDR[i]; pDL[i] = tDL[i]; }
    }
}

extern "C" void kernel_launch(void* const* d_in, const int* in_sizes, int n_in,
                              void* d_out, int out_size) {
    (void)in_sizes; (void)n_in; (void)out_size;
    const float* x = (const float*)d_in[0];
    float* out = (float*)d_out;

    dim3 block(BLOCK_X, 1, 1);
    dim3 grid(1, H / ROWS_PER_THREAD, 16 * 3);   // 1536 CTAs ~= one balanced wave
    census_kernel<<<grid, block>>>(x, out);
}